// round 5
// baseline (speedup 1.0000x reference)
#include <cuda_runtime.h>
#include <stdint.h>

#define IMG_H 1024
#define IMG_W 1280
#define NPIX (IMG_H * IMG_W)
#define NPTS 4194304

// Z-buffer scratch: key = (z_bits << 32) | point_index. Lexicographic min ==
// (min z, then min index) == reference's stable-argsort winner.
__device__ unsigned long long g_zbuf[NPIX];

__device__ __forceinline__ void splat_point(float x, float y, float z,
                                            unsigned int idx,
                                            float fx, float fy, float cx, float cy) {
    if (z > 0.0f) {
        // Match reference exactly: mul, div, add as separate IEEE-rounded ops,
        // then round-half-to-even. Exact div is required: 1-ULP drift flips
        // rintf on ~1e3 of 8.4M coords -> rel_err ~1e-2.
        float uf = __fadd_rn(__fdiv_rn(__fmul_rn(fx, x), z), cx);
        float vf = __fadd_rn(__fdiv_rn(__fmul_rn(fy, y), z), cy);
        int u = (int)rintf(uf);
        int v = (int)rintf(vf);
        if ((unsigned)u < (unsigned)IMG_W && (unsigned)v < (unsigned)IMG_H) {
            unsigned long long key =
                ((unsigned long long)__float_as_uint(z) << 32) | (unsigned long long)idx;
            atomicMin(&g_zbuf[v * IMG_W + u], key);  // return ignored -> RED
        }
    }
}

__global__ __launch_bounds__(256) void project_kernel(const float* __restrict__ points,
                                                      const float* __restrict__ Kmat) {
    int t = blockIdx.x * blockDim.x + threadIdx.x;  // handles 8 points
    const int noct = NPTS / 8;
    if (t >= noct) return;

    float fx = Kmat[0], cx = Kmat[2], fy = Kmat[4], cy = Kmat[5];

    const float4* p4 = reinterpret_cast<const float4*>(points);
    // Front-batch 6 streaming 128-bit loads (MLP=6), keep L2 for the zbuf.
    float4 a = __ldcs(&p4[t * 6 + 0]);  // x0 y0 z0 x1
    float4 b = __ldcs(&p4[t * 6 + 1]);  // y1 z1 x2 y2
    float4 c = __ldcs(&p4[t * 6 + 2]);  // z2 x3 y3 z3
    float4 d = __ldcs(&p4[t * 6 + 3]);  // x4 y4 z4 x5
    float4 e = __ldcs(&p4[t * 6 + 4]);  // y5 z5 x6 y6
    float4 f = __ldcs(&p4[t * 6 + 5]);  // z6 x7 y7 z7

    unsigned int base = (unsigned int)(t * 8);
    splat_point(a.x, a.y, a.z, base + 0, fx, fy, cx, cy);
    splat_point(a.w, b.x, b.y, base + 1, fx, fy, cx, cy);
    splat_point(b.z, b.w, c.x, base + 2, fx, fy, cx, cy);
    splat_point(c.y, c.z, c.w, base + 3, fx, fy, cx, cy);
    splat_point(d.x, d.y, d.z, base + 4, fx, fy, cx, cy);
    splat_point(d.w, e.x, e.y, base + 5, fx, fy, cx, cy);
    splat_point(e.z, e.w, f.x, base + 6, fx, fy, cx, cy);
    splat_point(f.y, f.z, f.w, base + 7, fx, fy, cx, cy);
}

// Fetch color[idx] (3 floats at idx*3) with exactly TWO divergent LDG.64s
// instead of three LDG.32s: base = (idx*3) & ~1 is 8B-aligned and the two
// float2 loads [base], [base+2] cover idx*3 .. idx*3+2 for either parity.
// (Overread of +1 float only when idx*3 is even; last index NPTS-1 has
// idx*3 odd, so never reads past the end of colors.)
__device__ __forceinline__ void fetch_color(unsigned int lo,
                                            const float* __restrict__ colors,
                                            float& r, float& g, float& b) {
    r = 0.0f; g = 0.0f; b = 0.0f;
    if (lo != 0xFFFFFFFFu) {            // idx < 2^22, sentinel low word = ~0
        unsigned int e = lo * 3u;
        unsigned int base = e & ~1u;
        const float2* cp = reinterpret_cast<const float2*>(colors + base);
        float2 a0 = __ldg(&cp[0]);
        float2 a1 = __ldg(&cp[1]);
        bool odd = (e & 1u) != 0u;
        r = odd ? a0.y : a0.x;
        g = odd ? a1.x : a0.y;
        b = odd ? a1.y : a1.x;
    }
}

__global__ __launch_bounds__(256) void gather_kernel(const float* __restrict__ colors,
                                                     float* __restrict__ out) {
    int t = blockIdx.x * blockDim.x + threadIdx.x;  // handles 8 pixels
    if (t >= NPIX / 8) return;

    // Each uint4 = {lo0, hi0, lo1, hi1} of two 64-bit keys; only low words needed.
    const uint4* zb = reinterpret_cast<const uint4*>(g_zbuf);
    uint4 q0 = zb[t * 4 + 0];
    uint4 q1 = zb[t * 4 + 1];
    uint4 q2 = zb[t * 4 + 2];
    uint4 q3 = zb[t * 4 + 3];

    float c[24];
    fetch_color(q0.x, colors, c[0],  c[1],  c[2]);
    fetch_color(q0.z, colors, c[3],  c[4],  c[5]);
    fetch_color(q1.x, colors, c[6],  c[7],  c[8]);
    fetch_color(q1.z, colors, c[9],  c[10], c[11]);
    fetch_color(q2.x, colors, c[12], c[13], c[14]);
    fetch_color(q2.z, colors, c[15], c[16], c[17]);
    fetch_color(q3.x, colors, c[18], c[19], c[20]);
    fetch_color(q3.z, colors, c[21], c[22], c[23]);

    float4* o4 = reinterpret_cast<float4*>(out);  // 96B per thread, 16B aligned
#pragma unroll
    for (int i = 0; i < 6; i++) {
        o4[t * 6 + i] = make_float4(c[i * 4 + 0], c[i * 4 + 1],
                                    c[i * 4 + 2], c[i * 4 + 3]);
    }
}

extern "C" void kernel_launch(void* const* d_in, const int* in_sizes, int n_in,
                              void* d_out, int out_size) {
    const float* points = (const float*)d_in[0];
    const float* colors = (const float*)d_in[1];
    const float* Kmat   = (const float*)d_in[2];
    float* out = (float*)d_out;

    // Reset z-buffer to all-ones sentinel via a memset node (graph-capturable,
    // no allocation). 0xFF bytes == 0xFFFFFFFFFFFFFFFF keys.
    void* zbuf_ptr = nullptr;
    cudaGetSymbolAddress(&zbuf_ptr, g_zbuf);
    cudaMemsetAsync(zbuf_ptr, 0xFF, NPIX * sizeof(unsigned long long));

    {
        int threads = 256;
        int noct = NPTS / 8;
        int blocks = (noct + threads - 1) / threads;
        project_kernel<<<blocks, threads>>>(points, Kmat);
    }
    {
        int threads = 256;
        int blocks = (NPIX / 8 + threads - 1) / threads;
        gather_kernel<<<blocks, threads>>>(colors, out);
    }
}

// round 6
// speedup vs baseline: 1.3767x; 1.3767x over previous
#include <cuda_runtime.h>
#include <stdint.h>

#define IMG_H 1024
#define IMG_W 1280
#define NPIX (IMG_H * IMG_W)
#define NPTS 4194304

// Z-buffer scratch: key = (z_bits << 32) | point_index. Lexicographic min ==
// (min z, then min index) == reference's stable-argsort winner.
__device__ unsigned long long g_zbuf[NPIX];

__device__ __forceinline__ void splat_point(float x, float y, float z,
                                            unsigned int idx,
                                            float fx, float fy, float cx, float cy) {
    if (z > 0.0f) {
        // Match reference exactly: mul, div, add as separate IEEE-rounded ops,
        // then round-half-to-even. Exact div is required: 1-ULP drift flips
        // rintf on ~1e3 of 8.4M coords -> rel_err ~1e-2.
        float uf = __fadd_rn(__fdiv_rn(__fmul_rn(fx, x), z), cx);
        float vf = __fadd_rn(__fdiv_rn(__fmul_rn(fy, y), z), cy);
        int u = (int)rintf(uf);
        int v = (int)rintf(vf);
        if ((unsigned)u < (unsigned)IMG_W && (unsigned)v < (unsigned)IMG_H) {
            unsigned long long key =
                ((unsigned long long)__float_as_uint(z) << 32) | (unsigned long long)idx;
            atomicMin(&g_zbuf[v * IMG_W + u], key);  // return ignored -> RED
        }
    }
}

__global__ __launch_bounds__(256) void project_kernel(const float* __restrict__ points,
                                                      const float* __restrict__ Kmat) {
    int t = blockIdx.x * blockDim.x + threadIdx.x;  // handles 8 points
    const int noct = NPTS / 8;
    if (t >= noct) return;

    float fx = Kmat[0], cx = Kmat[2], fy = Kmat[4], cy = Kmat[5];

    const float4* p4 = reinterpret_cast<const float4*>(points);
    // Front-batch 6 streaming 128-bit loads (MLP=6), keep L2 for the zbuf.
    float4 a = __ldcs(&p4[t * 6 + 0]);  // x0 y0 z0 x1
    float4 b = __ldcs(&p4[t * 6 + 1]);  // y1 z1 x2 y2
    float4 c = __ldcs(&p4[t * 6 + 2]);  // z2 x3 y3 z3
    float4 d = __ldcs(&p4[t * 6 + 3]);  // x4 y4 z4 x5
    float4 e = __ldcs(&p4[t * 6 + 4]);  // y5 z5 x6 y6
    float4 f = __ldcs(&p4[t * 6 + 5]);  // z6 x7 y7 z7

    unsigned int base = (unsigned int)(t * 8);
    splat_point(a.x, a.y, a.z, base + 0, fx, fy, cx, cy);
    splat_point(a.w, b.x, b.y, base + 1, fx, fy, cx, cy);
    splat_point(b.z, b.w, c.x, base + 2, fx, fy, cx, cy);
    splat_point(c.y, c.z, c.w, base + 3, fx, fy, cx, cy);
    splat_point(d.x, d.y, d.z, base + 4, fx, fy, cx, cy);
    splat_point(d.w, e.x, e.y, base + 5, fx, fy, cx, cy);
    splat_point(e.z, e.w, f.x, base + 6, fx, fy, cx, cy);
    splat_point(f.y, f.z, f.w, base + 7, fx, fy, cx, cy);
}

// Fetch color[idx] (3 floats at idx*3) with exactly TWO divergent LDG.64s
// instead of three LDG.32s: base = (idx*3) & ~1 is 8B-aligned and the two
// float2 loads [base], [base+2] cover idx*3 .. idx*3+2 for either parity.
// (Overread of +1 float only when idx*3 is even; last index NPTS-1 has
// idx*3 odd, so never reads past the end of colors.)
__device__ __forceinline__ void fetch_color(unsigned int lo,
                                            const float* __restrict__ colors,
                                            float& r, float& g, float& b) {
    r = 0.0f; g = 0.0f; b = 0.0f;
    if (lo != 0xFFFFFFFFu) {            // idx < 2^22, sentinel low word = ~0
        unsigned int e = lo * 3u;
        unsigned int base = e & ~1u;
        const float2* cp = reinterpret_cast<const float2*>(colors + base);
        float2 a0 = __ldg(&cp[0]);
        float2 a1 = __ldg(&cp[1]);
        bool odd = (e & 1u) != 0u;
        r = odd ? a0.y : a0.x;
        g = odd ? a1.x : a0.y;
        b = odd ? a1.y : a1.x;
    }
}

__global__ __launch_bounds__(256) void gather_kernel(const float* __restrict__ colors,
                                                     float* __restrict__ out) {
    int t = blockIdx.x * blockDim.x + threadIdx.x;  // handles 4 pixels
    if (t >= NPIX / 4) return;

    // Two uint4 loads = four 64-bit keys; only the low words are needed
    // (idx < 2^22; sentinel low word = 0xFFFFFFFF).
    const uint4* zb = reinterpret_cast<const uint4*>(g_zbuf);
    uint4 q0 = zb[t * 2 + 0];
    uint4 q1 = zb[t * 2 + 1];

    float c[12];
    fetch_color(q0.x, colors, c[0], c[1], c[2]);
    fetch_color(q0.z, colors, c[3], c[4], c[5]);
    fetch_color(q1.x, colors, c[6], c[7], c[8]);
    fetch_color(q1.z, colors, c[9], c[10], c[11]);

    float4* o4 = reinterpret_cast<float4*>(out);  // 48B per thread, 16B aligned
    o4[t * 3 + 0] = make_float4(c[0], c[1], c[2], c[3]);
    o4[t * 3 + 1] = make_float4(c[4], c[5], c[6], c[7]);
    o4[t * 3 + 2] = make_float4(c[8], c[9], c[10], c[11]);
}

extern "C" void kernel_launch(void* const* d_in, const int* in_sizes, int n_in,
                              void* d_out, int out_size) {
    const float* points = (const float*)d_in[0];
    const float* colors = (const float*)d_in[1];
    const float* Kmat   = (const float*)d_in[2];
    float* out = (float*)d_out;

    // Reset z-buffer to all-ones sentinel via a memset node (graph-capturable,
    // no allocation). 0xFF bytes == 0xFFFFFFFFFFFFFFFF keys.
    void* zbuf_ptr = nullptr;
    cudaGetSymbolAddress(&zbuf_ptr, g_zbuf);
    cudaMemsetAsync(zbuf_ptr, 0xFF, NPIX * sizeof(unsigned long long));

    {
        int threads = 256;
        int noct = NPTS / 8;
        int blocks = (noct + threads - 1) / threads;
        project_kernel<<<blocks, threads>>>(points, Kmat);
    }
    {
        int threads = 256;
        int blocks = (NPIX / 4 + threads - 1) / threads;
        gather_kernel<<<blocks, threads>>>(colors, out);
    }
}